// round 15
// baseline (speedup 1.0000x reference)
#include <cuda_runtime.h>
#include <math_constants.h>

// Problem shape
#define BB 8
#define HH 3
#define PP 4096
#define NPTS (BB * PP)
#define CH 256                   // chunk size (both I and J side)
#define NCH (PP / CH)            // 16 chunks per batch
#define NSLOT (CH / 2)           // 128 packed J-slots
#define TP 128                   // threads per block (4 warps)
#define BLKB (NCH * (NCH + 1) / 2)   // 136 triangular blocks per batch
#define NBLK 128

// per-(head,point) min as uint bits of nonneg float; reset to 0x7F7F7F7F
__device__ unsigned int g_minbits[HH * NPTS];
__device__ float g_partial[NBLK];

typedef unsigned long long u64;

// ---- f32x2 helpers ---------------------------------------------------------
__device__ __forceinline__ u64 pack2(float lo, float hi) {
    u64 d;
    asm("mov.b64 %0, {%1, %2};" : "=l"(d) : "f"(lo), "f"(hi));
    return d;
}
__device__ __forceinline__ u64 fma2(u64 a, u64 b, u64 c) {
    u64 d;
    asm("fma.rn.f32x2 %0, %1, %2, %3;" : "=l"(d) : "l"(a), "l"(b), "l"(c));
    return d;
}
__device__ __forceinline__ u64 add2(u64 a, u64 b) {
    u64 d;
    asm("add.rn.f32x2 %0, %1, %2;" : "=l"(d) : "l"(a), "l"(b));
    return d;
}
__device__ __forceinline__ void unpack2(u64 t, float& lo, float& hi) {
    asm("mov.b64 {%0, %1}, %2;" : "=f"(lo), "=f"(hi) : "l"(t));
}

// normalized plane normals + offset for batch b
__device__ __forceinline__ void load_normals(const float* __restrict__ planes,
                                             int b, float nx[HH], float ny[HH],
                                             float nz[HH], float nc[HH]) {
#pragma unroll
    for (int h = 0; h < HH; h++) {
        const float* pl = planes + (b * HH + h) * 4;
        float x = pl[0], y = pl[1], z = pl[2];
        float nn = x * x + y * y + z * z;
        float inv = rsqrtf(nn);
        inv = inv * (1.5f - 0.5f * nn * inv * inv);
        nx[h] = x * inv; ny[h] = y * inv; nz[h] = z * inv; nc[h] = pl[3];
    }
}

// ---------------------------------------------------------------------------
// Symmetric chamfer, broadcast-I / register-J.
// Block = (chunk ci, chunk cj), ci<=cj, 256 pts each. Lane permanently owns
// 4 packed J-slots (data + mins in registers, ZERO main-loop smem traffic).
// All 32 lanes process the SAME I-point per step (broadcast LDS, conflict-
// free); the I-side min is reduced across lanes with a shfl_xor tree and
// stored once (each warp owns 64 distinct I-points).
// v(p,q) = w_p + w_q - 2 p.q + 4 d_p d_q  (= |p - reflect_h(q)|^2, exact).
// ---------------------------------------------------------------------------
__global__ __launch_bounds__(TP)
void chamfer_kernel(const float* __restrict__ planes,
                    const float* __restrict__ pts) {
    __shared__ u64   sIc[7][CH];       // I constants (broadcast): 14 KB
    __shared__ u64   sJ[7][NSLOT];     // J staging: 7 KB
    __shared__ float sImin[HH][CH];    // per-I mins: 3 KB
    float* sJm = (float*)&sIc[0][0];   // J-merge scratch reuses sIc (12 KB)

    const int t    = threadIdx.x;
    const int lane = t & 31;
    const int w    = t >> 5;
    const int b    = blockIdx.z;

    // triangular decode: (ci, cj) with ci <= cj
    int f = blockIdx.x, ci = 0;
    while (f >= NCH - ci) { f -= NCH - ci; ci++; }
    const int cj = ci + f;

    float nx[HH], ny[HH], nz[HH], nc[HH];
    load_normals(planes, b, nx, ny, nz, nc);

    // ---- stage J-chunk (one slot = 2 points per thread; NSLOT == TP) ----
    {
        const float* q = pts + (b * PP + cj * CH + 2 * t) * 3;
        float x0 = q[0], y0 = q[1], z0 = q[2];
        float x1 = q[3], y1 = q[4], z1 = q[5];
        sJ[0][t] = pack2(x0, x1);
        sJ[1][t] = pack2(y0, y1);
        sJ[2][t] = pack2(z0, z1);
        sJ[3][t] = pack2(x0*x0 + y0*y0 + z0*z0, x1*x1 + y1*y1 + z1*z1);
#pragma unroll
        for (int h = 0; h < HH; h++) {
            float d0 = 2.f * (nx[h] * x0 + ny[h] * y0 + nz[h] * z0 + nc[h]);
            float d1 = 2.f * (nx[h] * x1 + ny[h] * y1 + nz[h] * z1 + nc[h]);
            sJ[4 + h][t] = pack2(d0, d1);
        }
    }

    // ---- stage I-chunk constants (2 points per thread) ----
#pragma unroll
    for (int r = 0; r < 2; r++) {
        const int i = r * TP + t;
        const float* P = pts + (b * PP + ci * CH + i) * 3;
        float ax = P[0], ay = P[1], az = P[2];
        sIc[0][i] = pack2(-2.f * ax, -2.f * ax);
        sIc[1][i] = pack2(-2.f * ay, -2.f * ay);
        sIc[2][i] = pack2(-2.f * az, -2.f * az);
        float wp = ax * ax + ay * ay + az * az;
        sIc[3][i] = pack2(wp, wp);
#pragma unroll
        for (int h = 0; h < HH; h++) {
            float e = 2.f * (nx[h] * ax + ny[h] * ay + nz[h] * az + nc[h]);
            sIc[4 + h][i] = pack2(e, e);
        }
    }
    __syncthreads();

    // ---- lane's 4 permanent J slots into registers ----
    u64 jX[4], jY[4], jZ[4], jW[4], jD0[4], jD1[4], jD2[4];
    float jm0a[4], jm0b[4], jm1a[4], jm1b[4], jm2a[4], jm2b[4];
#pragma unroll
    for (int s = 0; s < 4; s++) {
        const int slot = s * 32 + lane;
        jX[s]  = sJ[0][slot]; jY[s]  = sJ[1][slot]; jZ[s] = sJ[2][slot];
        jW[s]  = sJ[3][slot];
        jD0[s] = sJ[4][slot]; jD1[s] = sJ[5][slot]; jD2[s] = sJ[6][slot];
        jm0a[s] = jm0b[s] = CUDART_INF_F;
        jm1a[s] = jm1b[s] = CUDART_INF_F;
        jm2a[s] = jm2b[s] = CUDART_INF_F;
    }

    // ---- main loop: warp w covers I-points [w*64, w*64+64) ----
#pragma unroll 2
    for (int i = w * 64; i < w * 64 + 64; i++) {
        const u64 MX = sIc[0][i], MY = sIc[1][i], MZ = sIc[2][i];
        const u64 WP = sIc[3][i];
        const u64 E0 = sIc[4][i], E1 = sIc[5][i], E2 = sIc[6][i];

        float c0 = CUDART_INF_F, c1 = CUDART_INF_F, c2 = CUDART_INF_F;
#pragma unroll
        for (int s = 0; s < 4; s++) {
            u64 acc = fma2(MX, jX[s], add2(jW[s], WP));
            acc = fma2(MY, jY[s], acc);
            acc = fma2(MZ, jZ[s], acc);
            u64 v0 = fma2(E0, jD0[s], acc);
            u64 v1 = fma2(E1, jD1[s], acc);
            u64 v2 = fma2(E2, jD2[s], acc);
            float a0, b0, a1, b1, a2, b2;
            unpack2(v0, a0, b0);
            unpack2(v1, a1, b1);
            unpack2(v2, a2, b2);
            // J-side register mins (zero traffic)
            jm0a[s] = fminf(jm0a[s], a0);  jm0b[s] = fminf(jm0b[s], b0);
            jm1a[s] = fminf(jm1a[s], a1);  jm1b[s] = fminf(jm1b[s], b1);
            jm2a[s] = fminf(jm2a[s], a2);  jm2b[s] = fminf(jm2b[s], b2);
            // I-side candidate
            c0 = fminf(c0, fminf(a0, b0));
            c1 = fminf(c1, fminf(a1, b1));
            c2 = fminf(c2, fminf(a2, b2));
        }
        // cross-lane min (3 interleaved shfl_xor trees)
#pragma unroll
        for (int o = 16; o; o >>= 1) {
            c0 = fminf(c0, __shfl_xor_sync(0xffffffffu, c0, o));
            c1 = fminf(c1, __shfl_xor_sync(0xffffffffu, c1, o));
            c2 = fminf(c2, __shfl_xor_sync(0xffffffffu, c2, o));
        }
        if (lane == 0) {
            sImin[0][i] = c0;
            sImin[1][i] = c1;
            sImin[2][i] = c2;
        }
    }
    __syncthreads();

    // ---- I-side epilogue: 2 points per thread ----
#pragma unroll
    for (int r = 0; r < 2; r++) {
        const int i = r * TP + t;
        const int idx = b * PP + ci * CH + i;
        atomicMin(&g_minbits[0 * NPTS + idx],
                  __float_as_uint(fmaxf(sImin[0][i], 0.f)));
        atomicMin(&g_minbits[1 * NPTS + idx],
                  __float_as_uint(fmaxf(sImin[1][i], 0.f)));
        atomicMin(&g_minbits[2 * NPTS + idx],
                  __float_as_uint(fmaxf(sImin[2][i], 0.f)));
    }

    // ---- J-side: dump per-warp partials (reuse sIc), merge, atomicMin ----
    {
        float* dst = sJm + (w * 32 + lane) * 24;
#pragma unroll
        for (int s = 0; s < 4; s++) {
            dst[s * 6 + 0] = jm0a[s]; dst[s * 6 + 1] = jm0b[s];
            dst[s * 6 + 2] = jm1a[s]; dst[s * 6 + 3] = jm1b[s];
            dst[s * 6 + 4] = jm2a[s]; dst[s * 6 + 5] = jm2b[s];
        }
    }
    __syncthreads();

    // thread t merges slot t = s*32+l across the 4 warps
    {
        const int s = t >> 5, l = t & 31;
        const int j0 = b * PP + cj * CH + 2 * (s * 32 + l);
#pragma unroll
        for (int i = 0; i < 6; i++) {
            const int off = l * 24 + s * 6 + i;
            float m = fminf(fminf(sJm[(0 * 32) * 24 + off],
                                  sJm[(1 * 32) * 24 + off]),
                            fminf(sJm[(2 * 32) * 24 + off],
                                  sJm[(3 * 32) * 24 + off]));
            const int head = i >> 1, half = i & 1;
            atomicMin(&g_minbits[head * NPTS + j0 + half],
                      __float_as_uint(fmaxf(m, 0.f)));
        }
    }
}

// ---------------------------------------------------------------------------
__global__ __launch_bounds__(256)
void combine_kernel() {
    __shared__ float red[256];
    const int i = blockIdx.x * 256 + threadIdx.x;

    float s = __uint_as_float(g_minbits[0 * NPTS + i])
            + __uint_as_float(g_minbits[1 * NPTS + i])
            + __uint_as_float(g_minbits[2 * NPTS + i]);

    red[threadIdx.x] = s;
    __syncthreads();
#pragma unroll
    for (int off = 128; off > 0; off >>= 1) {
        if (threadIdx.x < off) red[threadIdx.x] += red[threadIdx.x + off];
        __syncthreads();
    }
    if (threadIdx.x == 0) g_partial[blockIdx.x] = red[0];
}

__global__ __launch_bounds__(128)
void finalize_kernel(const float* __restrict__ planes,
                     float* __restrict__ out) {
    __shared__ float red[128];
    __shared__ float regs[BB];
    const int t = threadIdx.x;

    red[t] = g_partial[t];
    __syncthreads();
#pragma unroll
    for (int off = 64; off > 0; off >>= 1) {
        if (t < off) red[t] += red[t + off];
        __syncthreads();
    }

    if (t < BB) {
        float nx[HH], ny[HH], nz[HH], nc[HH];
        load_normals(planes, t, nx, ny, nz, nc);
        float acc = 0.0f;
#pragma unroll
        for (int i = 0; i < HH; i++)
#pragma unroll
            for (int j = 0; j < HH; j++) {
                float g = nx[i] * nx[j] + ny[i] * ny[j] + nz[i] * nz[j]
                        - (i == j ? 1.0f : 0.0f);
                acc += g * g;
            }
        regs[t] = sqrtf(acc);
    }
    __syncthreads();

    if (t == 0) {
        float reg = 0.0f;
#pragma unroll
        for (int b = 0; b < BB; b++) reg += regs[b];
        float refl = 2.0f * red[0] / (float)(BB * PP);  // cham_x == cham_y
        out[0] = refl + 25.0f * reg;
    }
}

// ---------------------------------------------------------------------------
extern "C" void kernel_launch(void* const* d_in, const int* in_sizes, int n_in,
                              void* d_out, int out_size) {
    const float* planes = (const float*)d_in[0];   // (8, 3, 4)
    const float* pts    = (const float*)d_in[1];   // (8, 4096, 3)
    // d_in[2], d_in[3] unused by the reference.

    void* mb = nullptr;
    cudaGetSymbolAddress(&mb, g_minbits);
    cudaMemsetAsync(mb, 0x7F, (size_t)HH * NPTS * sizeof(unsigned int));

    dim3 grid(BLKB, 1, BB);   // 136 x 8 = 1088 blocks
    chamfer_kernel<<<grid, TP>>>(planes, pts);

    combine_kernel<<<NBLK, 256>>>();
    finalize_kernel<<<1, 128>>>(planes, (float*)d_out);
}

// round 16
// speedup vs baseline: 1.3946x; 1.3946x over previous
#include <cuda_runtime.h>
#include <math_constants.h>

// Problem shape
#define BB 8
#define HH 3
#define PP 4096
#define NPTS (BB * PP)
#define ISUP 512                 // I-tile (register side)
#define JCH  256                 // J-tile (smem side)
#define NPAIR (JCH / 2)          // 128 packed J-pairs
#define TP 128                   // threads per block
#define IK 4                     // I points per thread
#define BLKB 72                  // symmetric (isup,jch) blocks per batch
#define SPLIT 2                  // s2-rotation split factor
#define NBLK 128

// per-(head,point) min as uint bits of nonneg float; reset to 0x7F7F7F7F
__device__ unsigned int g_minbits[HH * NPTS];
__device__ float g_partial[NBLK];
__device__ int   g_count = 0;

typedef unsigned long long u64;

// ---- f32x2 helpers ---------------------------------------------------------
__device__ __forceinline__ u64 pack2(float lo, float hi) {
    u64 d;
    asm("mov.b64 %0, {%1, %2};" : "=l"(d) : "f"(lo), "f"(hi));
    return d;
}
__device__ __forceinline__ u64 fma2(u64 a, u64 b, u64 c) {
    u64 d;
    asm("fma.rn.f32x2 %0, %1, %2, %3;" : "=l"(d) : "l"(a), "l"(b), "l"(c));
    return d;
}
__device__ __forceinline__ u64 add2(u64 a, u64 b) {
    u64 d;
    asm("add.rn.f32x2 %0, %1, %2;" : "=l"(d) : "l"(a), "l"(b));
    return d;
}
__device__ __forceinline__ void unpack2(u64 t, float& lo, float& hi) {
    asm("mov.b64 {%0, %1}, %2;" : "=f"(lo), "=f"(hi) : "l"(t));
}

// normalized plane normals + offset for batch b
__device__ __forceinline__ void load_normals(const float* __restrict__ planes,
                                             int b, float nx[HH], float ny[HH],
                                             float nz[HH], float nc[HH]) {
#pragma unroll
    for (int h = 0; h < HH; h++) {
        const float* pl = planes + (b * HH + h) * 4;
        float x = pl[0], y = pl[1], z = pl[2];
        float nn = x * x + y * y + z * z;
        float inv = rsqrtf(nn);
        inv = inv * (1.5f - 0.5f * nn * inv * inv);
        nx[h] = x * inv; ny[h] = y * inv; nz[h] = z * inv; nc[h] = pl[3];
    }
}

// ---------------------------------------------------------------------------
// Symmetric chamfer (R11 structure + s2-split): block = (I-super 512 x
// J-chunk 256, rotation-half). v(p,q) = w_p + w_q - 2 p.q + 4 d_p d_q
// updates BOTH p's and q's min. I-mins in registers; J-mins in warp-private
// smem with rotating exclusive slot ownership (race-free). Each block covers
// rotations s2 in [spl*16, spl*16+16); partial mins merge via atomicMin.
// ---------------------------------------------------------------------------
__global__ __launch_bounds__(TP)
void chamfer_kernel(const float* __restrict__ planes,
                    const float* __restrict__ pts) {
    __shared__ ulonglong2 sA[NPAIR];   // (x0,x1),(y0,y1)
    __shared__ ulonglong2 sB[NPAIR];   // (z0,z1),(w0,w1)
    __shared__ ulonglong2 sC[NPAIR];   // (4d0q0,4d0q1),(4d1q0,4d1q1)
    __shared__ u64        sD[NPAIR];   // (4d2q0,4d2q1)
    __shared__ u64        sJ[3][4][NPAIR];   // packed J-mins [head][warp][slot]

    const int t    = threadIdx.x;
    const int lane = t & 31;
    const int w    = t >> 5;
    const int spl  = blockIdx.y;       // rotation half
    const int b    = blockIdx.z;

    // decode (isup, jch): jch >= 2*isup, 72 pairs per batch
    int f = blockIdx.x, isup = 0;
    while (f >= 16 - 2 * isup) { f -= 16 - 2 * isup; isup++; }
    const int jch = 2 * isup + f;

    float nx[HH], ny[HH], nz[HH], nc[HH];
    load_normals(planes, b, nx, ny, nz, nc);

    // ---- stage J-chunk (one pair per thread) ----
    {
        const float* q = pts + (b * PP + jch * JCH + 2 * t) * 3;
        float x0 = q[0], y0 = q[1], z0 = q[2];
        float x1 = q[3], y1 = q[4], z1 = q[5];
        float w0 = x0 * x0 + y0 * y0 + z0 * z0;
        float w1 = x1 * x1 + y1 * y1 + z1 * z1;
        float d0[HH], d1[HH];
#pragma unroll
        for (int h = 0; h < HH; h++) {
            d0[h] = 2.f * (nx[h] * x0 + ny[h] * y0 + nz[h] * z0 + nc[h]);
            d1[h] = 2.f * (nx[h] * x1 + ny[h] * y1 + nz[h] * z1 + nc[h]);
        }
        ulonglong2 A, B, C;
        A.x = pack2(x0, x1);     A.y = pack2(y0, y1);
        B.x = pack2(z0, z1);     B.y = pack2(w0, w1);
        C.x = pack2(d0[0], d1[0]);
        C.y = pack2(d0[1], d1[1]);
        sA[t] = A; sB[t] = B; sC[t] = C;
        sD[t] = pack2(d0[2], d1[2]);
    }
    // init packed J-min arrays (+inf, +inf)
    {
        const u64 inf2 = pack2(CUDART_INF_F, CUDART_INF_F);
        for (int x = t; x < 3 * 4 * NPAIR; x += TP)
            (&sJ[0][0][0])[x] = inf2;
    }

    // ---- I constants: IK points per thread, stride TP ----
    u64 MX[IK], MY[IK], MZ[IK], WP[IK];
    u64 Q0[IK], Q1[IK], Q2[IK];
    float im0[IK], im1[IK], im2[IK];
#pragma unroll
    for (int k = 0; k < IK; k++) {
        const int idx = b * PP + isup * ISUP + k * TP + t;
        const float* P = pts + idx * 3;
        float ax = P[0], ay = P[1], az = P[2];
        float wp = ax * ax + ay * ay + az * az;
        float e0 = 2.f * (nx[0] * ax + ny[0] * ay + nz[0] * az + nc[0]);
        float e1 = 2.f * (nx[1] * ax + ny[1] * ay + nz[1] * az + nc[1]);
        float e2 = 2.f * (nx[2] * ax + ny[2] * ay + nz[2] * az + nc[2]);
        MX[k] = pack2(-2.f * ax, -2.f * ax);
        MY[k] = pack2(-2.f * ay, -2.f * ay);
        MZ[k] = pack2(-2.f * az, -2.f * az);
        WP[k] = pack2(wp, wp);
        Q0[k] = pack2(e0, e0);     // (2dp)*(2dq) = 4 dp dq
        Q1[k] = pack2(e1, e1);
        Q2[k] = pack2(e2, e2);
        im0[k] = im1[k] = im2[k] = CUDART_INF_F;
    }

    __syncthreads();

    // ---- main loop: this block covers rotations [spl*16, spl*16+16) ----
    for (int s2 = spl * (32 / SPLIT); s2 < (spl + 1) * (32 / SPLIT); s2++) {
        const int base = (lane + s2) & 31;
#pragma unroll
        for (int sub = 0; sub < 4; sub++) {
            const int slot = sub * 32 + base;
            ulonglong2 A = sA[slot];
            ulonglong2 B = sB[slot];
            ulonglong2 C = sC[slot];
            u64 D2 = sD[slot];

            float t00, t01, t10, t11, t20, t21;   // J-side trees
#pragma unroll
            for (int k = 0; k < IK; k++) {
                u64 acc = fma2(MX[k], A.x, add2(B.y, WP[k]));
                acc = fma2(MY[k], A.y, acc);
                acc = fma2(MZ[k], B.x, acc);
                u64 v0 = fma2(Q0[k], C.x, acc);
                u64 v1 = fma2(Q1[k], C.y, acc);
                u64 v2 = fma2(Q2[k], D2,  acc);
                float a0, b0, a1, b1, a2, b2;
                unpack2(v0, a0, b0);
                unpack2(v1, a1, b1);
                unpack2(v2, a2, b2);
                im0[k] = fminf(im0[k], fminf(a0, b0));
                im1[k] = fminf(im1[k], fminf(a1, b1));
                im2[k] = fminf(im2[k], fminf(a2, b2));
                if (k == 0) { t00 = a0; t01 = b0; t10 = a1; t11 = b1; t20 = a2; t21 = b2; }
                else {
                    t00 = fminf(t00, a0); t01 = fminf(t01, b0);
                    t10 = fminf(t10, a1); t11 = fminf(t11, b1);
                    t20 = fminf(t20, a2); t21 = fminf(t21, b2);
                }
            }
            // packed exclusive smem RMW (this lane owns these slots now)
            {
                float pa, pb;
                u64 o0 = sJ[0][w][slot];
                unpack2(o0, pa, pb);
                sJ[0][w][slot] = pack2(fminf(pa, t00), fminf(pb, t01));
                u64 o1 = sJ[1][w][slot];
                unpack2(o1, pa, pb);
                sJ[1][w][slot] = pack2(fminf(pa, t10), fminf(pb, t11));
                u64 o2 = sJ[2][w][slot];
                unpack2(o2, pa, pb);
                sJ[2][w][slot] = pack2(fminf(pa, t20), fminf(pb, t21));
            }
        }
        __syncwarp();
    }

    // ---- I-side epilogue ----
#pragma unroll
    for (int k = 0; k < IK; k++) {
        const int idx = b * PP + isup * ISUP + k * TP + t;
        atomicMin(&g_minbits[0 * NPTS + idx], __float_as_uint(fmaxf(im0[k], 0.f)));
        atomicMin(&g_minbits[1 * NPTS + idx], __float_as_uint(fmaxf(im1[k], 0.f)));
        atomicMin(&g_minbits[2 * NPTS + idx], __float_as_uint(fmaxf(im2[k], 0.f)));
    }

    __syncthreads();

    // ---- J-side merge: thread t owns slot t across the 4 warps ----
    {
        const int j0 = b * PP + jch * JCH + 2 * t;
#pragma unroll
        for (int h = 0; h < HH; h++) {
            float a0, b0, a1, b1;
            unpack2(sJ[h][0][t], a0, b0);
            unpack2(sJ[h][1][t], a1, b1);
            float ma = fminf(a0, a1), mb = fminf(b0, b1);
            unpack2(sJ[h][2][t], a0, b0);
            unpack2(sJ[h][3][t], a1, b1);
            ma = fminf(ma, fminf(a0, a1));
            mb = fminf(mb, fminf(b0, b1));
            atomicMin(&g_minbits[h * NPTS + j0],
                      __float_as_uint(fmaxf(ma, 0.f)));
            atomicMin(&g_minbits[h * NPTS + j0 + 1],
                      __float_as_uint(fmaxf(mb, 0.f)));
        }
    }
}

// ---------------------------------------------------------------------------
// Combine + finalize (fused): per-block sum of head-mins; last block adds
// the reg loss and writes the scalar output.
// ---------------------------------------------------------------------------
__global__ __launch_bounds__(256)
void combine_kernel(const float* __restrict__ planes,
                    float* __restrict__ out) {
    __shared__ float red[256];
    __shared__ bool  amLast;
    const int i = blockIdx.x * 256 + threadIdx.x;

    float s = __uint_as_float(g_minbits[0 * NPTS + i])
            + __uint_as_float(g_minbits[1 * NPTS + i])
            + __uint_as_float(g_minbits[2 * NPTS + i]);

    red[threadIdx.x] = s;
    __syncthreads();
#pragma unroll
    for (int off = 128; off > 0; off >>= 1) {
        if (threadIdx.x < off) red[threadIdx.x] += red[threadIdx.x + off];
        __syncthreads();
    }
    if (threadIdx.x == 0) {
        g_partial[blockIdx.x] = red[0];
        __threadfence();
        amLast = (atomicAdd(&g_count, 1) == NBLK - 1);
    }
    __syncthreads();
    if (!amLast) return;

    // last block: final reduce + reg loss
    float v = (threadIdx.x < NBLK) ? g_partial[threadIdx.x] : 0.0f;
    red[threadIdx.x] = v;
    __syncthreads();
#pragma unroll
    for (int off = 128; off > 0; off >>= 1) {
        if (threadIdx.x < off) red[threadIdx.x] += red[threadIdx.x + off];
        __syncthreads();
    }

    __shared__ float regs[BB];
    if (threadIdx.x < BB) {
        float nx[HH], ny[HH], nz[HH], nc[HH];
        load_normals(planes, threadIdx.x, nx, ny, nz, nc);
        float acc = 0.0f;
#pragma unroll
        for (int i2 = 0; i2 < HH; i2++)
#pragma unroll
            for (int j2 = 0; j2 < HH; j2++) {
                float g = nx[i2] * nx[j2] + ny[i2] * ny[j2] + nz[i2] * nz[j2]
                        - (i2 == j2 ? 1.0f : 0.0f);
                acc += g * g;
            }
        regs[threadIdx.x] = sqrtf(acc);
    }
    __syncthreads();

    if (threadIdx.x == 0) {
        float reg = 0.0f;
#pragma unroll
        for (int b = 0; b < BB; b++) reg += regs[b];
        float refl = 2.0f * red[0] / (float)(BB * PP);  // cham_x == cham_y
        out[0] = refl + 25.0f * reg;
        g_count = 0;   // reset for next graph replay (deterministic)
    }
}

// ---------------------------------------------------------------------------
extern "C" void kernel_launch(void* const* d_in, const int* in_sizes, int n_in,
                              void* d_out, int out_size) {
    const float* planes = (const float*)d_in[0];   // (8, 3, 4)
    const float* pts    = (const float*)d_in[1];   // (8, 4096, 3)
    // d_in[2], d_in[3] unused by the reference.

    void* mb = nullptr;
    cudaGetSymbolAddress(&mb, g_minbits);
    cudaMemsetAsync(mb, 0x7F, (size_t)HH * NPTS * sizeof(unsigned int));

    dim3 grid(BLKB, SPLIT, BB);   // 72 x 2 x 8 = 1152 blocks
    chamfer_kernel<<<grid, TP>>>(planes, pts);

    combine_kernel<<<NBLK, 256>>>(planes, (float*)d_out);
}

// round 17
// speedup vs baseline: 1.4024x; 1.0056x over previous
#include <cuda_runtime.h>
#include <math_constants.h>

// Problem shape
#define BB 8
#define HH 3
#define PP 4096
#define NPTS (BB * PP)
#define ISUP 512                 // I-tile (register side)
#define JCH  256                 // J-tile (smem side)
#define NPAIR (JCH / 2)          // 128 packed J-pairs
#define TP 128                   // threads per block
#define IK 4                     // I points per thread
#define BLKB 72                  // symmetric (isup,jch) blocks per batch
#define SPLIT 2                  // s2-rotation split factor
#define NBLK 64                  // combine blocks / partials

// per-(head,point) min as uint bits of nonneg float; reset to 0x7F7F7F7F
__device__ unsigned int g_minbits[HH * NPTS];
__device__ float g_partial[NBLK];
__device__ int   g_count = 0;

typedef unsigned long long u64;

// ---- f32x2 helpers ---------------------------------------------------------
__device__ __forceinline__ u64 pack2(float lo, float hi) {
    u64 d;
    asm("mov.b64 %0, {%1, %2};" : "=l"(d) : "f"(lo), "f"(hi));
    return d;
}
__device__ __forceinline__ u64 fma2(u64 a, u64 b, u64 c) {
    u64 d;
    asm("fma.rn.f32x2 %0, %1, %2, %3;" : "=l"(d) : "l"(a), "l"(b), "l"(c));
    return d;
}
__device__ __forceinline__ u64 add2(u64 a, u64 b) {
    u64 d;
    asm("add.rn.f32x2 %0, %1, %2;" : "=l"(d) : "l"(a), "l"(b));
    return d;
}
__device__ __forceinline__ void unpack2(u64 t, float& lo, float& hi) {
    asm("mov.b64 {%0, %1}, %2;" : "=f"(lo), "=f"(hi) : "l"(t));
}

// normalized plane normals + offset for batch b
__device__ __forceinline__ void load_normals(const float* __restrict__ planes,
                                             int b, float nx[HH], float ny[HH],
                                             float nz[HH], float nc[HH]) {
#pragma unroll
    for (int h = 0; h < HH; h++) {
        const float* pl = planes + (b * HH + h) * 4;
        float x = pl[0], y = pl[1], z = pl[2];
        float nn = x * x + y * y + z * z;
        float inv = rsqrtf(nn);
        inv = inv * (1.5f - 0.5f * nn * inv * inv);
        nx[h] = x * inv; ny[h] = y * inv; nz[h] = z * inv; nc[h] = pl[3];
    }
}

// ---------------------------------------------------------------------------
// Symmetric chamfer (R16, unchanged): block = (I-super 512 x J-chunk 256,
// rotation-half). v(p,q) = w_p + w_q - 2 p.q + 4 d_p d_q updates BOTH mins.
// I-mins in registers; J-mins in warp-private packed smem with rotating
// exclusive slot ownership (race-free).
// ---------------------------------------------------------------------------
__global__ __launch_bounds__(TP)
void chamfer_kernel(const float* __restrict__ planes,
                    const float* __restrict__ pts) {
    __shared__ ulonglong2 sA[NPAIR];
    __shared__ ulonglong2 sB[NPAIR];
    __shared__ ulonglong2 sC[NPAIR];
    __shared__ u64        sD[NPAIR];
    __shared__ u64        sJ[3][4][NPAIR];   // packed J-mins [head][warp][slot]

    const int t    = threadIdx.x;
    const int lane = t & 31;
    const int w    = t >> 5;
    const int spl  = blockIdx.y;
    const int b    = blockIdx.z;

    int f = blockIdx.x, isup = 0;
    while (f >= 16 - 2 * isup) { f -= 16 - 2 * isup; isup++; }
    const int jch = 2 * isup + f;

    float nx[HH], ny[HH], nz[HH], nc[HH];
    load_normals(planes, b, nx, ny, nz, nc);

    // ---- stage J-chunk ----
    {
        const float* q = pts + (b * PP + jch * JCH + 2 * t) * 3;
        float x0 = q[0], y0 = q[1], z0 = q[2];
        float x1 = q[3], y1 = q[4], z1 = q[5];
        float w0 = x0 * x0 + y0 * y0 + z0 * z0;
        float w1 = x1 * x1 + y1 * y1 + z1 * z1;
        float d0[HH], d1[HH];
#pragma unroll
        for (int h = 0; h < HH; h++) {
            d0[h] = 2.f * (nx[h] * x0 + ny[h] * y0 + nz[h] * z0 + nc[h]);
            d1[h] = 2.f * (nx[h] * x1 + ny[h] * y1 + nz[h] * z1 + nc[h]);
        }
        ulonglong2 A, B, C;
        A.x = pack2(x0, x1);     A.y = pack2(y0, y1);
        B.x = pack2(z0, z1);     B.y = pack2(w0, w1);
        C.x = pack2(d0[0], d1[0]);
        C.y = pack2(d0[1], d1[1]);
        sA[t] = A; sB[t] = B; sC[t] = C;
        sD[t] = pack2(d0[2], d1[2]);
    }
    {
        const u64 inf2 = pack2(CUDART_INF_F, CUDART_INF_F);
        for (int x = t; x < 3 * 4 * NPAIR; x += TP)
            (&sJ[0][0][0])[x] = inf2;
    }

    // ---- I constants ----
    u64 MX[IK], MY[IK], MZ[IK], WP[IK];
    u64 Q0[IK], Q1[IK], Q2[IK];
    float im0[IK], im1[IK], im2[IK];
#pragma unroll
    for (int k = 0; k < IK; k++) {
        const int idx = b * PP + isup * ISUP + k * TP + t;
        const float* P = pts + idx * 3;
        float ax = P[0], ay = P[1], az = P[2];
        float wp = ax * ax + ay * ay + az * az;
        float e0 = 2.f * (nx[0] * ax + ny[0] * ay + nz[0] * az + nc[0]);
        float e1 = 2.f * (nx[1] * ax + ny[1] * ay + nz[1] * az + nc[1]);
        float e2 = 2.f * (nx[2] * ax + ny[2] * ay + nz[2] * az + nc[2]);
        MX[k] = pack2(-2.f * ax, -2.f * ax);
        MY[k] = pack2(-2.f * ay, -2.f * ay);
        MZ[k] = pack2(-2.f * az, -2.f * az);
        WP[k] = pack2(wp, wp);
        Q0[k] = pack2(e0, e0);
        Q1[k] = pack2(e1, e1);
        Q2[k] = pack2(e2, e2);
        im0[k] = im1[k] = im2[k] = CUDART_INF_F;
    }

    __syncthreads();

    // ---- main loop: rotations [spl*16, spl*16+16) ----
    for (int s2 = spl * (32 / SPLIT); s2 < (spl + 1) * (32 / SPLIT); s2++) {
        const int base = (lane + s2) & 31;
#pragma unroll
        for (int sub = 0; sub < 4; sub++) {
            const int slot = sub * 32 + base;
            ulonglong2 A = sA[slot];
            ulonglong2 B = sB[slot];
            ulonglong2 C = sC[slot];
            u64 D2 = sD[slot];

            float t00, t01, t10, t11, t20, t21;
#pragma unroll
            for (int k = 0; k < IK; k++) {
                u64 acc = fma2(MX[k], A.x, add2(B.y, WP[k]));
                acc = fma2(MY[k], A.y, acc);
                acc = fma2(MZ[k], B.x, acc);
                u64 v0 = fma2(Q0[k], C.x, acc);
                u64 v1 = fma2(Q1[k], C.y, acc);
                u64 v2 = fma2(Q2[k], D2,  acc);
                float a0, b0, a1, b1, a2, b2;
                unpack2(v0, a0, b0);
                unpack2(v1, a1, b1);
                unpack2(v2, a2, b2);
                im0[k] = fminf(im0[k], fminf(a0, b0));
                im1[k] = fminf(im1[k], fminf(a1, b1));
                im2[k] = fminf(im2[k], fminf(a2, b2));
                if (k == 0) { t00 = a0; t01 = b0; t10 = a1; t11 = b1; t20 = a2; t21 = b2; }
                else {
                    t00 = fminf(t00, a0); t01 = fminf(t01, b0);
                    t10 = fminf(t10, a1); t11 = fminf(t11, b1);
                    t20 = fminf(t20, a2); t21 = fminf(t21, b2);
                }
            }
            {
                float pa, pb;
                u64 o0 = sJ[0][w][slot];
                unpack2(o0, pa, pb);
                sJ[0][w][slot] = pack2(fminf(pa, t00), fminf(pb, t01));
                u64 o1 = sJ[1][w][slot];
                unpack2(o1, pa, pb);
                sJ[1][w][slot] = pack2(fminf(pa, t10), fminf(pb, t11));
                u64 o2 = sJ[2][w][slot];
                unpack2(o2, pa, pb);
                sJ[2][w][slot] = pack2(fminf(pa, t20), fminf(pb, t21));
            }
        }
        __syncwarp();
    }

    // ---- I-side epilogue ----
#pragma unroll
    for (int k = 0; k < IK; k++) {
        const int idx = b * PP + isup * ISUP + k * TP + t;
        atomicMin(&g_minbits[0 * NPTS + idx], __float_as_uint(fmaxf(im0[k], 0.f)));
        atomicMin(&g_minbits[1 * NPTS + idx], __float_as_uint(fmaxf(im1[k], 0.f)));
        atomicMin(&g_minbits[2 * NPTS + idx], __float_as_uint(fmaxf(im2[k], 0.f)));
    }

    __syncthreads();

    // ---- J-side merge: thread t owns slot t across the 4 warps ----
    {
        const int j0 = b * PP + jch * JCH + 2 * t;
#pragma unroll
        for (int h = 0; h < HH; h++) {
            float a0, b0, a1, b1;
            unpack2(sJ[h][0][t], a0, b0);
            unpack2(sJ[h][1][t], a1, b1);
            float ma = fminf(a0, a1), mb = fminf(b0, b1);
            unpack2(sJ[h][2][t], a0, b0);
            unpack2(sJ[h][3][t], a1, b1);
            ma = fminf(ma, fminf(a0, a1));
            mb = fminf(mb, fminf(b0, b1));
            atomicMin(&g_minbits[h * NPTS + j0],
                      __float_as_uint(fmaxf(ma, 0.f)));
            atomicMin(&g_minbits[h * NPTS + j0 + 1],
                      __float_as_uint(fmaxf(mb, 0.f)));
        }
    }
}

// ---------------------------------------------------------------------------
// Lean combine + finalize: 64 blocks x 256 threads. Each thread: 3x LDG.64
// (2 points x 3 heads), 6 FADD, warp shfl reduce (fixed order ->
// deterministic), one __syncthreads. Last block reduces the 64 partials and
// adds the reg loss.
// ---------------------------------------------------------------------------
__global__ __launch_bounds__(256)
void combine_kernel(const float* __restrict__ planes,
                    float* __restrict__ out) {
    __shared__ float warpsum[8];
    __shared__ bool  amLast;
    const int t = threadIdx.x;
    const int lane = t & 31, w = t >> 5;
    const int i = (blockIdx.x * 256 + t) * 2;   // 2 points per thread

    const uint2* p0 = (const uint2*)&g_minbits[0 * NPTS + i];
    const uint2* p1 = (const uint2*)&g_minbits[1 * NPTS + i];
    const uint2* p2 = (const uint2*)&g_minbits[2 * NPTS + i];
    uint2 a = *p0, bq = *p1, c = *p2;
    float s = __uint_as_float(a.x)  + __uint_as_float(a.y)
            + __uint_as_float(bq.x) + __uint_as_float(bq.y)
            + __uint_as_float(c.x)  + __uint_as_float(c.y);

#pragma unroll
    for (int o = 16; o; o >>= 1)
        s += __shfl_xor_sync(0xffffffffu, s, o);
    if (lane == 0) warpsum[w] = s;
    __syncthreads();

    if (t == 0) {
        float blk = 0.f;
#pragma unroll
        for (int j = 0; j < 8; j++) blk += warpsum[j];
        g_partial[blockIdx.x] = blk;
        __threadfence();
        amLast = (atomicAdd(&g_count, 1) == NBLK - 1);
    }
    __syncthreads();
    if (!amLast) return;

    // final: 64 partials + reg loss
    __shared__ float regs[BB];
    float v = (t < NBLK) ? g_partial[t] : 0.0f;
#pragma unroll
    for (int o = 16; o; o >>= 1)
        v += __shfl_xor_sync(0xffffffffu, v, o);
    if (lane == 0) warpsum[w] = v;

    if (t < BB) {
        float nx[HH], ny[HH], nz[HH], nc[HH];
        load_normals(planes, t, nx, ny, nz, nc);
        float acc = 0.0f;
#pragma unroll
        for (int i2 = 0; i2 < HH; i2++)
#pragma unroll
            for (int j2 = 0; j2 < HH; j2++) {
                float g = nx[i2] * nx[j2] + ny[i2] * ny[j2] + nz[i2] * nz[j2]
                        - (i2 == j2 ? 1.0f : 0.0f);
                acc += g * g;
            }
        regs[t] = sqrtf(acc);
    }
    __syncthreads();

    if (t == 0) {
        float total = warpsum[0] + warpsum[1];   // partials live in warps 0,1
        float reg = 0.0f;
#pragma unroll
        for (int b = 0; b < BB; b++) reg += regs[b];
        float refl = 2.0f * total / (float)(BB * PP);  // cham_x == cham_y
        out[0] = refl + 25.0f * reg;
        g_count = 0;   // reset for next graph replay
    }
}

// ---------------------------------------------------------------------------
extern "C" void kernel_launch(void* const* d_in, const int* in_sizes, int n_in,
                              void* d_out, int out_size) {
    const float* planes = (const float*)d_in[0];   // (8, 3, 4)
    const float* pts    = (const float*)d_in[1];   // (8, 4096, 3)
    // d_in[2], d_in[3] unused by the reference.

    void* mb = nullptr;
    cudaGetSymbolAddress(&mb, g_minbits);
    cudaMemsetAsync(mb, 0x7F, (size_t)HH * NPTS * sizeof(unsigned int));

    dim3 grid(BLKB, SPLIT, BB);   // 72 x 2 x 8 = 1152 blocks
    chamfer_kernel<<<grid, TP>>>(planes, pts);

    combine_kernel<<<NBLK, 256>>>(planes, (float*)d_out);
}